// round 1
// baseline (speedup 1.0000x reference)
#include <cuda_runtime.h>
#include <cstdint>

#define HID   100
#define GROWS 400
#define TENC  4096
#define TDEC  4096
#define NCLS  6
#define NTHREADS 448   // 14 warps: 0-12 matvec (400 rows), warp 13 logits

typedef unsigned long long ull;

// ---- packed f32x2 helpers (Blackwell) ----
__device__ __forceinline__ ull fma2(ull a, ull b, ull c) {
    ull d;
    asm("fma.rn.f32x2 %0, %1, %2, %3;" : "=l"(d) : "l"(a), "l"(b), "l"(c));
    return d;
}
__device__ __forceinline__ ull add2(ull a, ull b) {
    ull d;
    asm("add.rn.f32x2 %0, %1, %2;" : "=l"(d) : "l"(a), "l"(b));
    return d;
}

// ---- fast accurate transcendental (EX2 + RCP, ~1e-7 rel err) ----
__device__ __forceinline__ float ex2f(float x) {
    float y; asm("ex2.approx.f32 %0, %1;" : "=f"(y) : "f"(x)); return y;
}
__device__ __forceinline__ float rcpf(float x) {
    float y; asm("rcp.approx.f32 %0, %1;" : "=f"(y) : "f"(x)); return y;
}
#define LOG2E 1.4426950408889634f
__device__ __forceinline__ float sigmoidf_fast(float x) {
    // 1 / (1 + e^-x)
    return rcpf(1.0f + ex2f(-LOG2E * x));
}
__device__ __forceinline__ float tanhf_fast(float x) {
    // (e^2x - 1)/(e^2x + 1) = 1 - 2/(1 + e^2x)
    return 1.0f - 2.0f * rcpf(1.0f + ex2f((2.0f * LOG2E) * x));
}

// dot of 100-element register-resident row (50 packed f32x2) with shared h
__device__ __forceinline__ float dot100(const ull* __restrict__ w, unsigned hb) {
    ull a0 = 0ull, a1 = 0ull, a2 = 0ull, a3 = 0ull;
#pragma unroll
    for (int m = 0; m < 25; ++m) {
        ull h0, h1;
        asm volatile("ld.shared.v2.b64 {%0, %1}, [%2];"
                     : "=l"(h0), "=l"(h1) : "r"(hb + 16 * m));
        if (m & 1) { a2 = fma2(w[2*m], h0, a2); a3 = fma2(w[2*m+1], h1, a3); }
        else       { a0 = fma2(w[2*m], h0, a0); a1 = fma2(w[2*m+1], h1, a1); }
    }
    ull s = add2(add2(a0, a2), add2(a1, a3));
    float lo, hi;
    asm("mov.b64 {%0, %1}, %2;" : "=f"(lo), "=f"(hi) : "l"(s));
    return lo + hi;
}

__global__ void __launch_bounds__(NTHREADS, 1)
lstm_encdec_kernel(const float* __restrict__ x,      // [TENC,3]
                   const int*   __restrict__ y,      // [TDEC]
                   const float* __restrict__ eWih,   // [400,3]
                   const float* __restrict__ eWhh,   // [400,100]
                   const float* __restrict__ ebih,   // [400]
                   const float* __restrict__ ebhh,   // [400]
                   const float* __restrict__ dWih,   // [400,1]
                   const float* __restrict__ dWhh,   // [400,100]
                   const float* __restrict__ dbih,   // [400]
                   const float* __restrict__ dbhh,   // [400]
                   const float* __restrict__ linW,   // [6,100]
                   const float* __restrict__ linb,   // [6]
                   float* __restrict__ out)          // [TDEC,6]
{
    __shared__ __align__(16) float sh_h[HID];     // hidden state (single buffer)
    __shared__ float sh_g[GROWS];                 // post-activation gates
    __shared__ float sh_lw[NCLS * HID];           // lin_W copy (keeps regs low)
    __shared__ float sh_lb[NCLS];

    const int tid  = threadIdx.x;
    const int wid  = tid >> 5;
    const int lane = tid & 31;
    const bool mv  = (tid < GROWS);               // owns a gate row
    const int  r   = mv ? tid : 0;

    // ---- init ----
    if (tid < HID) sh_h[tid] = 0.0f;
    if (tid < NCLS) { out[(TDEC - 1) * NCLS + tid] = 0.0f; sh_lb[tid] = linb[tid]; }
    for (int i = tid; i < NCLS * HID; i += NTHREADS) sh_lw[i] = linW[i];
    float c = 0.0f;                                // cell state, thread j<100 owns c[j]

    // logits-warp lane mapping: lane = ls*8 + ll ; ls in 0..3 = 25-chunk, ll = class
    const int ls = lane >> 3;
    const int ll = lane & 7;

    const unsigned hb = (unsigned)__cvta_generic_to_shared(sh_h);

    // ---- encoder phase weights -> registers ----
    ull w[50];
    float wi0, wi1, wi2, bias;
    {
        const ull* p = reinterpret_cast<const ull*>(eWhh + r * HID);
#pragma unroll
        for (int k = 0; k < 50; ++k) w[k] = p[k];
        wi0 = eWih[r * 3 + 0];
        wi1 = eWih[r * 3 + 1];
        wi2 = eWih[r * 3 + 2];
        bias = ebih[r] + ebhh[r];
    }
    __syncthreads();

    // ================= encoder: 4096 steps =================
#pragma unroll 1
    for (int t = 0; t < TENC; ++t) {
        if (wid != 13) {
            const float x0 = x[t * 3 + 0];
            const float x1 = x[t * 3 + 1];
            const float x2 = x[t * 3 + 2];
            float g = dot100(w, hb);
            g = fmaf(wi0, x0, fmaf(wi1, x1, fmaf(wi2, x2, g + bias)));
            float act = (r >= 200 && r < 300) ? tanhf_fast(g) : sigmoidf_fast(g);
            if (mv) sh_g[r] = act;
        }
        __syncthreads();   // gates ready
        if (tid < HID) {
            const float gi = sh_g[tid];
            const float gf = sh_g[tid + 100];
            const float gg = sh_g[tid + 200];
            const float go = sh_g[tid + 300];
            c = fmaf(gf, c, gi * gg);
            sh_h[tid] = go * tanhf_fast(c);
        }
        __syncthreads();   // h ready
    }

    // ---- decoder phase weights -> registers (overwrite) ----
    {
        const ull* p = reinterpret_cast<const ull*>(dWhh + r * HID);
#pragma unroll
        for (int k = 0; k < 50; ++k) w[k] = p[k];
        wi0 = dWih[r];
        bias = dbih[r] + dbhh[r];
    }
    // no barrier needed: only thread-private registers changed

    // ================= decoder: 4096 iterations =================
    // iteration s: logits warp emits logits of step s-1 (h currently in sh_h),
    // overlapped with matvec of step s (active for s < TDEC-1 = 4095 steps).
#pragma unroll 1
    for (int s = 0; s < TDEC; ++s) {
        if (wid == 13) {
            if (s >= 1) {
                float acc = 0.0f;
                const float* lwp = sh_lw + ll * HID + ls * 25;   // ll>=6 reads row<6 pattern guarded below
                if (ll < NCLS) {
#pragma unroll
                    for (int k = 0; k < 25; ++k)
                        acc = fmaf(lwp[k], sh_h[ls * 25 + k], acc);
                }
                acc += __shfl_xor_sync(0xffffffffu, acc, 8);
                acc += __shfl_xor_sync(0xffffffffu, acc, 16);
                if (ls == 0 && ll < NCLS)
                    out[(s - 1) * NCLS + ll] = acc + sh_lb[ll];
            }
        } else if (s < TDEC - 1) {
            const float yf = (float)y[s];           // teacher forcing (ratio==1)
            float g = dot100(w, hb);
            g = fmaf(wi0, yf, g + bias);
            float act = (r >= 200 && r < 300) ? tanhf_fast(g) : sigmoidf_fast(g);
            if (mv) sh_g[r] = act;
        }
        __syncthreads();   // gates ready
        if (tid < HID && s < TDEC - 1) {
            const float gi = sh_g[tid];
            const float gf = sh_g[tid + 100];
            const float gg = sh_g[tid + 200];
            const float go = sh_g[tid + 300];
            c = fmaf(gf, c, gi * gg);
            sh_h[tid] = go * tanhf_fast(c);
        }
        __syncthreads();   // h ready
    }
}

extern "C" void kernel_launch(void* const* d_in, const int* in_sizes, int n_in,
                              void* d_out, int out_size) {
    const float* x     = (const float*)d_in[0];
    const int*   y     = (const int*)  d_in[1];
    const float* eWih  = (const float*)d_in[2];
    const float* eWhh  = (const float*)d_in[3];
    const float* ebih  = (const float*)d_in[4];
    const float* ebhh  = (const float*)d_in[5];
    const float* dWih  = (const float*)d_in[6];
    const float* dWhh  = (const float*)d_in[7];
    const float* dbih  = (const float*)d_in[8];
    const float* dbhh  = (const float*)d_in[9];
    const float* linW  = (const float*)d_in[10];
    const float* linb  = (const float*)d_in[11];
    float* out = (float*)d_out;

    lstm_encdec_kernel<<<1, NTHREADS>>>(x, y, eWih, eWhh, ebih, ebhh,
                                        dWih, dWhh, dbih, dbhh, linW, linb, out);
}